// round 16
// baseline (speedup 1.0000x reference)
#include <cuda_runtime.h>
#include <cuda_bf16.h>
#include <cuda_fp16.h>

// ---------------------------------------------------------------------------
// Net_67765993996461  R14: n-major layouts (spikes [b][n][ci], u [b][n][co]).
// Conv B-fill = 4x cp.async per thread (no STS, no gather regs); single sync
// per tap. LIF kernels c-fastest lane mapping (fully coalesced). 2-way fp16
// weight split (pre-scaled 2^10). 64KB smem, 3 CTAs/SM.
// ---------------------------------------------------------------------------

#define TAUF ((float)(10.0 / 7.0))
constexpr float INV_TAU = 1.0f / TAUF;

constexpr int BB   = 32;
constexpr int CC   = 64;
constexpr int TT_  = 129;
constexpr int TIN  = 128;
constexpr int MM   = 40;
constexpr int N_SP = TT_ * MM;        // 5160
constexpr int LANES = BB * CC * MM;   // 81920
constexpr int VOL   = BB * CC * N_SP;

// conv smem: A = 2 x (128 rows x 128B), B = 2 x (128 n-rows x 128B)
constexpr int A_TILE = 128 * 128;                  // 16384
constexpr int B_TILE = 128 * 128;                  // 16384
constexpr int B_OFF  = 2 * A_TILE;                 // 32768
constexpr int SMEM_BYTES = B_OFF + 2 * B_TILE;     // 65536 -> 3 CTAs/SM

constexpr float WSCALE   = 1024.0f;
constexpr float WUNSCALE = 1.0f / 1024.0f;

// Scratch (n-major layouts)
__device__ __half g_s1[VOL];                       // [b][n][ci]  (128B rows)
__device__ float  g_u [VOL];                       // [b][n][co]  (256B rows)
__device__ __half g_s2[VOL];                       // [b][n][ci]
__device__ __half g_w2s[12 * 2 * CC * CC];         // [tap][split][co][ci]
__device__ __half g_w3s[12 * 2 * CC * CC];
__device__ float  g_ssum[BB * CC * MM];            // [b][c*40+m]

// ---------------------------------------------------------------------------
// conv1 + LIF: thread -> (b, m, c) with c fastest (coalesced n-major stores).
// x loads are lane-uniform (broadcast).
// ---------------------------------------------------------------------------
__global__ void conv1_lif_kernel(const float* __restrict__ x,
                                 const float* __restrict__ w1) {
    int idx = blockIdx.x * blockDim.x + threadIdx.x;
    if (idx >= LANES) return;
    int c = idx & 63;
    int m = (idx >> 6) % MM;
    int b = idx / (CC * MM);

    float w[12];
#pragma unroll
    for (int k = 0; k < 12; k++) w[k] = w1[c * 12 + k];

    const float* xb = x + (size_t)b * TIN * MM;

    float a0[3], a1[3], a2[3], a3[3];
    auto load_row = [&](float* d, int t) {
        if (t >= 0 && t < TIN) {
            const float* r = xb + t * MM;
            d[0] = (m > 0)      ? r[m - 1] : 0.f;
            d[1] = r[m];
            d[2] = (m < MM - 1) ? r[m + 1] : 0.f;
        } else {
            d[0] = d[1] = d[2] = 0.f;
        }
    };
#pragma unroll
    for (int j = 0; j < 3; j++) { a0[j] = 0.f; a1[j] = 0.f; }
    load_row(a2, 0);
    load_row(a3, 1);

    __half* sp = g_s1 + ((size_t)b * N_SP + m) * CC + c;
    float v = 0.f;
    for (int t = 0; t < TT_; t++) {
        float u = 0.f;
#pragma unroll
        for (int j = 0; j < 3; j++) {
            u += w[0 + j] * a0[j];
            u += w[3 + j] * a1[j];
            u += w[6 + j] * a2[j];
            u += w[9 + j] * a3[j];
        }
        v = v + (u - v) * INV_TAU;
        float s = (v >= 1.f) ? 1.f : 0.f;
        sp[(size_t)t * MM * CC] = __float2half_rn(s);
        v = (v >= 1.f) ? 0.f : v;
#pragma unroll
        for (int j = 0; j < 3; j++) { a0[j] = a1[j]; a1[j] = a2[j]; a2[j] = a3[j]; }
        load_row(a3, t + 2);
    }
}

// ---------------------------------------------------------------------------
// 2-way fp16 split (RZ), weights pre-scaled by 2^10. Layout [tap][split][co][ci].
// ---------------------------------------------------------------------------
__global__ void wsplit_kernel(const float* __restrict__ wa,
                              const float* __restrict__ wb) {
    int which = blockIdx.y;
    const float* w = which ? wb : wa;
    __half* ws = which ? g_w3s : g_w2s;
    int i = blockIdx.x * blockDim.x + threadIdx.x;   // i = co*768 + ci*12 + tap
    if (i >= CC * CC * 12) return;
    int co  = i / 768;
    int r   = i - co * 768;
    int ci  = r / 12;
    int tap = r - ci * 12;
    float v = w[i] * WSCALE;
    __half h0 = __float2half_rz(v);
    float r1 = v - __half2float(h0);
    __half h1 = __float2half_rz(r1);
    ws[((tap * 2 + 0) * CC + co) * CC + ci] = h0;
    ws[((tap * 2 + 1) * CC + co) * CC + ci] = h1;
}

// ---------------------------------------------------------------------------
__device__ __forceinline__ void mma16816(float* d, const unsigned* a, const unsigned* b) {
    asm volatile(
        "mma.sync.aligned.m16n8k16.row.col.f32.f16.f16.f32 "
        "{%0,%1,%2,%3}, {%4,%5,%6,%7}, {%8,%9}, {%0,%1,%2,%3};\n"
        : "+f"(d[0]), "+f"(d[1]), "+f"(d[2]), "+f"(d[3])
        : "r"(a[0]), "r"(a[1]), "r"(a[2]), "r"(a[3]), "r"(b[0]), "r"(b[1]));
}
__device__ __forceinline__ void ldsm_x4(unsigned addr, unsigned& r0, unsigned& r1,
                                        unsigned& r2, unsigned& r3) {
    asm volatile("ldmatrix.sync.aligned.m8n8.x4.shared.b16 {%0,%1,%2,%3}, [%4];\n"
                 : "=r"(r0), "=r"(r1), "=r"(r2), "=r"(r3) : "r"(addr));
}
__device__ __forceinline__ void ldsm_x4_t(unsigned addr, unsigned& r0, unsigned& r1,
                                          unsigned& r2, unsigned& r3) {
    asm volatile("ldmatrix.sync.aligned.m8n8.x4.trans.shared.b16 {%0,%1,%2,%3}, [%4];\n"
                 : "=r"(r0), "=r"(r1), "=r"(r2), "=r"(r3) : "r"(addr));
}
__device__ __forceinline__ unsigned smem_u32(const void* p) {
    return (unsigned)__cvta_generic_to_shared(p);
}
__device__ __forceinline__ void cp_async16(unsigned dst, const void* src) {
    asm volatile("cp.async.cg.shared.global [%0], [%1], 16;\n"
                 :: "r"(dst), "l"(src) : "memory");
}
#define CP_COMMIT() asm volatile("cp.async.commit_group;\n" ::: "memory")
#define CP_WAIT0()  asm volatile("cp.async.wait_group 0;\n" ::: "memory")

// ---------------------------------------------------------------------------
// Conv GEMM: 64co x 128n per CTA, 8 warps (32co x 32n), tap-decomposed.
// A (weights [split][co][ci], 128 rows x 128B, XOR-swizzled): cp.async 2-buf.
// B (spikes  [n][ci],        128 rows x 128B, XOR-swizzled): cp.async 2-buf.
// ONE __syncthreads per tap; fills of tap+1 issued before domma(tap).
// ---------------------------------------------------------------------------
template <int LAYER, int DT, int PT, int DM, int PM>
__global__ __launch_bounds__(256, 3) void conv_mma_kernel() {
    extern __shared__ __align__(128) char sm[];
    unsigned sbase = smem_u32(sm);
    unsigned Ab[2] = {sbase, sbase + A_TILE};
    unsigned Bb[2] = {sbase + B_OFF, sbase + B_OFF + B_TILE};

    const __half* __restrict__ in = (LAYER == 2) ? g_s1 : g_s2;
    const __half* __restrict__ ws = (LAYER == 2) ? g_w2s : g_w3s;

    int b  = blockIdx.y;
    int n0 = blockIdx.x * 128;
    int tid  = threadIdx.x;
    int warp = tid >> 5, lane = tid & 31;
    int wco = (warp >> 2) * 32;
    int wn  = (warp & 3) * 32;

    const __half* inb = in + (size_t)b * N_SP * CC;

    int nl   = tid & 127;               // B-fill row (n local)
    int half = tid >> 7;                // ci half (0: ci0-31, 1: ci32-63)
    int ng  = n0 + nl;
    int tt0 = ng / MM;
    int mm0 = ng - tt0 * MM;

    float acc[2][4][4];
#pragma unroll
    for (int i = 0; i < 2; i++)
#pragma unroll
        for (int j = 0; j < 4; j++)
#pragma unroll
            for (int q = 0; q < 4; q++) acc[i][j][q] = 0.f;

    // A fill: 1024 uint4 per tap (2 splits x 64 rows x 128B), cp.async
    auto fillA = [&](int tap, unsigned Ad) {
        const uint4* wsrc = (const uint4*)(ws + (size_t)tap * 2 * CC * CC);
#pragma unroll
        for (int r = 0; r < 4; r++) {
            int i = tid + r * 256;
            int row = i >> 3, q = i & 7;
            unsigned dst = Ad + row * 128 + ((q ^ (row & 7)) << 4);
            cp_async16(dst, wsrc + i);
        }
    };

    // B fill: thread -> (row nl, 64B = 4x16B of its ci half), cp.async or zeros
    auto fillB = [&](int tap, unsigned Bd) {
        int kt = tap / 3, km = tap - kt * 3;
        int tt = tt0 + DT * kt - PT;
        int mm = mm0 + DM * km - PM;
        bool p = (tt >= 0) & (tt < TT_) & (mm >= 0) & (mm < MM);
        unsigned rowbase = Bd + nl * 128;
        unsigned xr = (unsigned)(nl & 7);
        if (p) {
            const char* src = (const char*)(inb + ((size_t)tt * MM + mm) * CC + half * 32);
#pragma unroll
            for (int j = 0; j < 4; j++) {
                unsigned seg = (unsigned)(half * 4 + j);
                cp_async16(rowbase + ((seg ^ xr) << 4), src + j * 16);
            }
        } else {
            uint4 z = make_uint4(0, 0, 0, 0);
#pragma unroll
            for (int j = 0; j < 4; j++) {
                unsigned seg = (unsigned)(half * 4 + j);
                *(uint4*)(sm + (rowbase - sbase) + ((seg ^ xr) << 4)) = z;
            }
        }
    };

    auto domma = [&](unsigned Ad, unsigned Bd) {
#pragma unroll
        for (int ks = 0; ks < 4; ks++) {
            unsigned bf[4][2];
#pragma unroll
            for (int g = 0; g < 2; g++) {
                int nrow = wn + g * 16 + (lane & 15);
                int seg  = 2 * ks + (lane >> 4);
                unsigned addr = Bd + nrow * 128 + (((unsigned)(seg ^ (nrow & 7))) << 4);
                unsigned q0, q1, q2, q3;
                ldsm_x4_t(addr, q0, q1, q2, q3);
                // transposed-tile pairing: n0-7 = {q0,q2}, n8-15 = {q1,q3}
                bf[2 * g][0] = q0; bf[2 * g][1] = q2;
                bf[2 * g + 1][0] = q1; bf[2 * g + 1][1] = q3;
            }
#pragma unroll
            for (int s = 0; s < 2; s++) {
#pragma unroll
                for (int mf = 0; mf < 2; mf++) {
                    int row = s * 64 + wco + mf * 16 + (lane & 15);
                    int j = ks * 2 + (lane >> 4);
                    unsigned addr = Ad + row * 128 + (((unsigned)(j ^ (row & 7))) << 4);
                    unsigned a[4];
                    ldsm_x4(addr, a[0], a[1], a[2], a[3]);
#pragma unroll
                    for (int nf = 0; nf < 4; nf++)
                        mma16816(acc[mf][nf], a, bf[nf]);
                }
            }
        }
    };

    // prologue
    fillA(0, Ab[0]);
    fillB(0, Bb[0]);
    CP_COMMIT();
    CP_WAIT0();
    __syncthreads();

#pragma unroll 1
    for (int tap = 0; tap < 12; tap++) {
        int cur = tap & 1, nxt = cur ^ 1;
        if (tap < 11) {
            fillA(tap + 1, Ab[nxt]);
            fillB(tap + 1, Bb[nxt]);
            CP_COMMIT();
        }
        domma(Ab[cur], Bb[cur]);
        if (tap < 11) CP_WAIT0();
        __syncthreads();
    }

    // epilogue: g_u[b][n][co] (256B rows)
    int lrow = lane >> 2, lk = (lane & 3) * 2;
    float* outb = g_u + (size_t)b * N_SP * CC;
#pragma unroll
    for (int mf = 0; mf < 2; mf++) {
#pragma unroll
        for (int nf = 0; nf < 4; nf++) {
            int co = wco + mf * 16 + lrow;
            int n  = n0 + wn + nf * 8 + lk;
#pragma unroll
            for (int e = 0; e < 2; e++) {
                if (n + e < N_SP) {
                    float* p = outb + (size_t)(n + e) * CC + co;
                    p[0] = acc[mf][nf][0 + e] * WUNSCALE;
                    p[8] = acc[mf][nf][2 + e] * WUNSCALE;
                }
            }
        }
    }
}

// ---------------------------------------------------------------------------
// LIF over t, thread -> (b, m, c) c-fastest. Coalesced n-major load/store.
// ---------------------------------------------------------------------------
__global__ void lif2_kernel() {
    int idx = blockIdx.x * blockDim.x + threadIdx.x;
    if (idx >= LANES) return;
    int c = idx & 63;
    int m = (idx >> 6) % MM;
    int b = idx / (CC * MM);
    const float* up = g_u + ((size_t)b * N_SP + m) * CC + c;
    __half* sp = g_s2 + ((size_t)b * N_SP + m) * CC + c;
    const size_t ST = (size_t)MM * CC;
    float v = 0.f;
#pragma unroll 1
    for (int t = 0; t < 128; t += 8) {
        float xr[8];
#pragma unroll
        for (int j = 0; j < 8; j++) xr[j] = up[(t + j) * ST];
        __half sr[8];
#pragma unroll
        for (int j = 0; j < 8; j++) {
            v = v + (xr[j] - v) * INV_TAU;
            sr[j] = __float2half_rn((v >= 1.f) ? 1.f : 0.f);
            v = (v >= 1.f) ? 0.f : v;
        }
#pragma unroll
        for (int j = 0; j < 8; j++) sp[(t + j) * ST] = sr[j];
    }
    {
        float x0 = up[128 * ST];
        v = v + (x0 - v) * INV_TAU;
        sp[128 * ST] = __float2half_rn((v >= 1.f) ? 1.f : 0.f);
    }
}

// ---------------------------------------------------------------------------
// LIF3 + time-sum fused: writes g_ssum[b][c*40+m].
// ---------------------------------------------------------------------------
__global__ void lif3_tsum_kernel() {
    int idx = blockIdx.x * blockDim.x + threadIdx.x;
    if (idx >= LANES) return;
    int c = idx & 63;
    int m = (idx >> 6) % MM;
    int b = idx / (CC * MM);
    const float* up = g_u + ((size_t)b * N_SP + m) * CC + c;
    const size_t ST = (size_t)MM * CC;
    float v = 0.f, a = 0.f;
#pragma unroll 1
    for (int t = 0; t < 128; t += 8) {
        float xr[8];
#pragma unroll
        for (int j = 0; j < 8; j++) xr[j] = up[(t + j) * ST];
#pragma unroll
        for (int j = 0; j < 8; j++) {
            v = v + (xr[j] - v) * INV_TAU;
            if (v >= 1.f) { a += 1.f; v = 0.f; }
        }
    }
    {
        float x0 = up[128 * ST];
        v = v + (x0 - v) * INV_TAU;
        if (v >= 1.f) a += 1.f;
    }
    g_ssum[(size_t)b * (CC * MM) + c * MM + m] = a;
}

// ---------------------------------------------------------------------------
__global__ void fc_kernel(const float* __restrict__ wf,
                          const float* __restrict__ bf,
                          float* __restrict__ y) {
    int b = blockIdx.x, j = blockIdx.y;
    int tid = threadIdx.x;
    const float* sb = g_ssum + b * (CC * MM);
    const float* wj = wf + j * (CC * MM);
    float acc = 0.f;
    for (int i = tid; i < CC * MM; i += 128) acc += sb[i] * wj[i];
    __shared__ float red[128];
    red[tid] = acc;
    __syncthreads();
    for (int s = 64; s > 0; s >>= 1) {
        if (tid < s) red[tid] += red[tid + s];
        __syncthreads();
    }
    if (tid == 0) y[b * 12 + j] = red[0] * (1.0f / 129.0f) + bf[j];
}

// ---------------------------------------------------------------------------
extern "C" void kernel_launch(void* const* d_in, const int* in_sizes, int n_in,
                              void* d_out, int out_size) {
    const float* x  = (const float*)d_in[0];
    const float* w1 = (const float*)d_in[1];
    const float* w2 = (const float*)d_in[2];
    const float* w3 = (const float*)d_in[3];
    const float* wf = (const float*)d_in[4];
    const float* bf = (const float*)d_in[5];
    float* y = (float*)d_out;

    static int smem_set = 0;
    if (!smem_set) {
        cudaFuncSetAttribute(conv_mma_kernel<2, 4, 6, 3, 3>,
                             cudaFuncAttributeMaxDynamicSharedMemorySize, SMEM_BYTES);
        cudaFuncSetAttribute(conv_mma_kernel<3, 16, 24, 9, 9>,
                             cudaFuncAttributeMaxDynamicSharedMemorySize, SMEM_BYTES);
        smem_set = 1;
    }

    {
        dim3 grid((CC * CC * 12 + 255) / 256, 2);
        wsplit_kernel<<<grid, 256>>>(w2, w3);
    }

    conv1_lif_kernel<<<(LANES + 255) / 256, 256>>>(x, w1);

    {
        dim3 grid((N_SP + 127) / 128, BB);
        conv_mma_kernel<2, 4, 6, 3, 3><<<grid, 256, SMEM_BYTES>>>();
    }
    lif2_kernel<<<(LANES + 255) / 256, 256>>>();

    {
        dim3 grid((N_SP + 127) / 128, BB);
        conv_mma_kernel<3, 16, 24, 9, 9><<<grid, 256, SMEM_BYTES>>>();
    }
    lif3_tsum_kernel<<<(LANES + 255) / 256, 256>>>();

    {
        dim3 grid(BB, 12);
        fc_kernel<<<grid, 128>>>(wf, bf, y);
    }
}